// round 16
// baseline (speedup 1.0000x reference)
#include <cuda_runtime.h>
#include <cuda.h>
#include <cstdint>

// axon_layer: dual-exponential PSP scan.
//   m_t = m_{t-1}*dm + x_t ; s_t = s_{t-1}*ds + x_t ; psp_t = (m_t - s_t)*v0
//
// TMA 2D tensor-tile movers (one cp.async.bulk.tensor.2d per 64-row x 160B
// stage, load AND store) -> warp LSU only does the scan's LDS/STS.
// 2 load stages + 1 store stage = 30.8 KB smem -> 7 blocks/SM -> capacity
// 1036 blocks; grid 2048 -> 1.98 waves -> 98.9% scheduling utilization
// (R15: 5 blocks/SM, 2.77 -> 3 waves, 92%). 14 warps/SM.
//
// Inputs: [0] input_spikes f32 [B,F,T]  [1] decay_m f32 [F]
//         [2] decay_s f32 [F]           [3] v_0 f32 scalar
// Output: psps [B,F,T] then m_T [B,F] then s_T [B,F].

#define AX_THREADS 64
#define AX_ROWS    64
#define AX_T       400
#define AX_CHF     40                      // floats per chunk per row (160 B)
#define AX_CH4     (AX_CHF / 4)            // 10 quads
#define AX_NCHUNK  10
#define AX_NL      2                       // load ring stages
#define AX_STAGEB  (AX_ROWS * AX_CHF * 4)  // 10240 B per stage
#define SM_S       (AX_NL * AX_STAGEB)     // store stage offset  (20480)
#define SM_MBAR    (SM_S + AX_STAGEB)      // mbarriers offset    (30720)
#define SM_TOTAL   (SM_MBAR + 64)          // 30784 B -> 7 blocks/SM

__device__ __forceinline__ uint32_t ax_s32(const void* p) {
    return (uint32_t)__cvta_generic_to_shared(p);
}
__device__ __forceinline__ void ax_mbar_init(uint32_t mbar, uint32_t cnt) {
    asm volatile("mbarrier.init.shared.b64 [%0], %1;" :: "r"(mbar), "r"(cnt) : "memory");
}
__device__ __forceinline__ void ax_expect_tx(uint32_t mbar, uint32_t bytes) {
    asm volatile("mbarrier.arrive.expect_tx.shared.b64 _, [%0], %1;"
                 :: "r"(mbar), "r"(bytes) : "memory");
}
__device__ __forceinline__ void ax_wait_parity(uint32_t mbar, uint32_t parity) {
    uint32_t done;
    asm volatile(
        "{\n\t.reg .pred p;\n\t"
        "mbarrier.try_wait.parity.acquire.cta.shared::cta.b64 p, [%1], %2;\n\t"
        "selp.b32 %0, 1, 0, p;\n\t}"
        : "=r"(done) : "r"(mbar), "r"(parity) : "memory");
    if (!done) {
        asm volatile(
            "{\n\t.reg .pred P1;\n\t"
            "WL_%=:\n\t"
            "mbarrier.try_wait.parity.acquire.cta.shared::cta.b64 P1, [%0], %1, 0x989680;\n\t"
            "@P1 bra.uni WD_%=;\n\t"
            "bra.uni WL_%=;\n\t"
            "WD_%=:\n\t}"
            :: "r"(mbar), "r"(parity) : "memory");
    }
}
__device__ __forceinline__ void ax_tma_load2d(uint32_t sdst, const CUtensorMap* map,
                                              int x, int y, uint32_t mbar) {
    asm volatile(
        "cp.async.bulk.tensor.2d.shared::cta.global.tile.mbarrier::complete_tx::bytes "
        "[%0], [%1, {%2, %3}], [%4];"
        :: "r"(sdst), "l"(map), "r"(x), "r"(y), "r"(mbar) : "memory");
}
__device__ __forceinline__ void ax_tma_store2d(const CUtensorMap* map,
                                               int x, int y, uint32_t ssrc) {
    asm volatile(
        "cp.async.bulk.tensor.2d.global.shared::cta.tile.bulk_group "
        "[%0, {%1, %2}], [%3];"
        :: "l"(map), "r"(x), "r"(y), "r"(ssrc) : "memory");
}
__device__ __forceinline__ void ax_bulk_commit() {
    asm volatile("cp.async.bulk.commit_group;" ::: "memory");
}
__device__ __forceinline__ void ax_bulk_wait_read0() {
    asm volatile("cp.async.bulk.wait_group.read 0;" ::: "memory");
}
__device__ __forceinline__ void ax_bulk_wait_all() {
    asm volatile("cp.async.bulk.wait_group 0;" ::: "memory");
}

extern __shared__ char ax_smem[];

__global__ void __launch_bounds__(AX_THREADS)
axon_tma2_kernel(const __grid_constant__ CUtensorMap in_map,
                 const __grid_constant__ CUtensorMap out_map,
                 const float* __restrict__ decay_m,
                 const float* __restrict__ decay_s,
                 const float* __restrict__ v0p,
                 float* __restrict__ out,
                 int F, long long n_rows)
{
    const int tid = threadIdx.x;
    const long long row0 = (long long)blockIdx.x * AX_ROWS;
    const long long my_row = row0 + tid;

    const float dm = __ldg(&decay_m[(int)(my_row % F)]);
    const float ds = __ldg(&decay_s[(int)(my_row % F)]);
    const float v0 = __ldg(v0p);

    const uint32_t sbase = ax_s32(ax_smem);
    const uint32_t mb0 = sbase + SM_MBAR;

    if (tid == 0) {
#pragma unroll
        for (int p = 0; p < AX_NL; ++p) ax_mbar_init(mb0 + p * 8, 1);
        asm volatile("fence.mbarrier_init.release.cluster;" ::: "memory");
    }
    __syncthreads();

    // ---- prologue: TMA-load chunks 0..1 into the 2 load stages ----
    if (tid == 0) {
#pragma unroll
        for (int p = 0; p < AX_NL; ++p) {
            ax_expect_tx(mb0 + p * 8, AX_STAGEB);
            ax_tma_load2d(sbase + p * AX_STAGEB, &in_map,
                          p * AX_CHF, (int)row0, mb0 + p * 8);
        }
    }

    float m = 0.0f, s = 0.0f;
    float4* S4 = (float4*)(ax_smem + SM_S) + tid * AX_CH4;

    for (int ch = 0; ch < AX_NCHUNK; ++ch) {
        const int st = ch & (AX_NL - 1);
        const uint32_t parity = (uint32_t)((ch >> 1) & 1);

        ax_wait_parity(mb0 + st * 8, parity);   // load stage st has chunk ch
        if (tid == 0) ax_bulk_wait_read0();     // previous store drained S
        __syncthreads();

        const float4* L4 = (const float4*)(ax_smem + st * AX_STAGEB) + tid * AX_CH4;

        // ---- sequential scan of this thread's row segment: L -> S ----
#pragma unroll
        for (int q = 0; q < AX_CH4; ++q) {
            float4 v = L4[q];
            float4 o;
            m = fmaf(m, dm, v.x); s = fmaf(s, ds, v.x); o.x = (m - s) * v0;
            m = fmaf(m, dm, v.y); s = fmaf(s, ds, v.y); o.y = (m - s) * v0;
            m = fmaf(m, dm, v.z); s = fmaf(s, ds, v.z); o.z = (m - s) * v0;
            m = fmaf(m, dm, v.w); s = fmaf(s, ds, v.w); o.w = (m - s) * v0;
            S4[q] = o;
        }
        asm volatile("fence.proxy.async.shared::cta;" ::: "memory");
        __syncthreads();

        // ---- one TMA store of S + one TMA refill of stage st ----
        if (tid == 0) {
            ax_tma_store2d(&out_map, ch * AX_CHF, (int)row0, sbase + SM_S);
            ax_bulk_commit();
            if (ch + AX_NL < AX_NCHUNK) {
                ax_expect_tx(mb0 + st * 8, AX_STAGEB);
                ax_tma_load2d(sbase + st * AX_STAGEB, &in_map,
                              (ch + AX_NL) * AX_CHF, (int)row0, mb0 + st * 8);
            }
        }
    }

    // ---- final states ----
    const long long psps = n_rows * AX_T;
    out[psps + my_row]          = m;
    out[psps + n_rows + my_row] = s;

    if (tid == 0) ax_bulk_wait_all();   // drain outstanding TMA stores
}

extern "C" void kernel_launch(void* const* d_in, const int* in_sizes, int n_in,
                              void* d_out, int out_size)
{
    const float* x   = (const float*)d_in[0];
    const float* dmv = (const float*)d_in[1];
    const float* dsv = (const float*)d_in[2];
    const float* v0p = (const float*)d_in[3];
    float* out = (float*)d_out;

    const int F = in_sizes[1];                       // 4096
    const long long total = (long long)in_sizes[0];  // B*F*T
    const long long n_rows = total / AX_T;           // 131072
    const int grid = (int)(n_rows / AX_ROWS);        // 2048

    // --- tensor maps (driver entry point via runtime; no -lcuda link) ---
    typedef CUresult (*EncodeFn)(CUtensorMap*, CUtensorMapDataType, cuuint32_t,
                                 void*, const cuuint64_t*, const cuuint64_t*,
                                 const cuuint32_t*, const cuuint32_t*,
                                 CUtensorMapInterleave, CUtensorMapSwizzle,
                                 CUtensorMapL2promotion, CUtensorMapFloatOOBfill);
    static EncodeFn enc = nullptr;
    if (!enc) {
        cudaDriverEntryPointQueryResult qr;
        void* fp = nullptr;
        cudaGetDriverEntryPoint("cuTensorMapEncodeTiled", &fp,
                                cudaEnableDefault, &qr);
        enc = (EncodeFn)fp;
    }

    cuuint64_t dims[2]    = { (cuuint64_t)AX_T, (cuuint64_t)n_rows };
    cuuint64_t strides[1] = { (cuuint64_t)AX_T * sizeof(float) };   // 1600 B
    cuuint32_t box[2]     = { AX_CHF, AX_ROWS };                    // 40 x 64
    cuuint32_t es[2]      = { 1, 1 };

    CUtensorMap in_map, out_map;
    enc(&in_map, CU_TENSOR_MAP_DATA_TYPE_FLOAT32, 2, (void*)x,
        dims, strides, box, es,
        CU_TENSOR_MAP_INTERLEAVE_NONE, CU_TENSOR_MAP_SWIZZLE_NONE,
        CU_TENSOR_MAP_L2_PROMOTION_L2_128B, CU_TENSOR_MAP_FLOAT_OOB_FILL_NONE);
    enc(&out_map, CU_TENSOR_MAP_DATA_TYPE_FLOAT32, 2, (void*)out,
        dims, strides, box, es,
        CU_TENSOR_MAP_INTERLEAVE_NONE, CU_TENSOR_MAP_SWIZZLE_NONE,
        CU_TENSOR_MAP_L2_PROMOTION_L2_128B, CU_TENSOR_MAP_FLOAT_OOB_FILL_NONE);

    static bool attr_set = false;
    if (!attr_set) {
        cudaFuncSetAttribute(axon_tma2_kernel,
                             cudaFuncAttributeMaxDynamicSharedMemorySize,
                             SM_TOTAL);
        attr_set = true;
    }

    axon_tma2_kernel<<<grid, AX_THREADS, SM_TOTAL>>>(
        in_map, out_map, dmv, dsv, v0p, out, F, n_rows);
}